// round 8
// baseline (speedup 1.0000x reference)
#include <cuda_runtime.h>
#include <cuda_bf16.h>
#include <cstdint>

// ---------------------------------------------------------------------------
// SupGCL_GConv: 3x [GEMM(64x64)+bias+relu] interleaved with 2x high-pass
// graph filter:  out = z*(1-inv) - (sum_{j->i} z[j])*inv,  inv = 1/(deg*cnt)
//   deg[i] = outdeg(i)+1, cnt[i] = indeg(i)+1  (self loops folded in algebra)
//
// R7: push->pull. Build CSC (edges bucketed by dst) once per launch, then the
// filter is an atomic-free gather: 16 lanes per dst node accumulate neighbor
// rows in registers and write the finalized filtered row. Deletes all L2
// atomic RMW + acc zeroing traffic. GEMM inner loop re-vectorized (float4
// x-loads over k) to cut shared-memory pressure 2.5x.
// ---------------------------------------------------------------------------

#define N_NODES 100000
#define D 64
#define N_EDGES 1200000
#define SCAN_T 1024

__device__ __align__(16) float g_zA[(size_t)N_NODES * D];   // gemm1 out
__device__ __align__(16) float g_zB[(size_t)N_NODES * D];   // gemm2 out
__device__ __align__(16) float g_zf[(size_t)N_NODES * D];   // filtered z
__device__ __align__(8)  int2  g_edge[N_EDGES];             // decoded (src,dst)
__device__ int g_csrc[N_EDGES];                             // CSC: src per dst-sorted slot
__device__ int g_rowptr[N_NODES];                           // CSC row starts
__device__ int g_cur[N_NODES];                              // bucket cursors
__device__ int g_deg[N_NODES];                              // outdeg+1
__device__ int g_cnt[N_NODES];                              // indeg+1
__device__ int g_is64;

// ---------------------------------------------------------------------------
__global__ void detect_dtype_kernel(const long long* __restrict__ ei) {
    // int64 buffer -> first 8 values are valid node ids; int32 viewed as int64
    // packs two ids -> >= 2^32 w.h.p.
    if (blockIdx.x == 0 && threadIdx.x == 0) {
        bool ok = true;
        for (int i = 0; i < 8; i++) {
            long long v = ei[i];
            if (v < 0 || v >= N_NODES) ok = false;
        }
        g_is64 = ok ? 1 : 0;
    }
}

__global__ void init_counts_kernel(int n) {
    int i = blockIdx.x * blockDim.x + threadIdx.x;
    if (i < n) { g_deg[i] = 1; g_cnt[i] = 1; }   // self loops
}

// Decode edge indices (int32 or int64) to int2 AND count degrees.
__global__ void edge_prep_kernel(const void* __restrict__ ei, int E, int n) {
    int e = blockIdx.x * blockDim.x + threadIdx.x;
    if (e >= E) return;
    int s, t;
    if (g_is64) {
        s = (int)((const long long*)ei)[e];
        t = (int)((const long long*)ei)[E + e];
    } else {
        s = ((const int*)ei)[e];
        t = ((const int*)ei)[E + e];
    }
    if ((unsigned)s >= (unsigned)n) s = 0;   // defensive: wrong beats crash
    if ((unsigned)t >= (unsigned)n) t = 0;
    g_edge[e] = make_int2(s, t);
    atomicAdd(&g_deg[s], 1);
    atomicAdd(&g_cnt[t], 1);
}

// Single-block exclusive scan of indeg (= cnt-1) -> rowptr, cursors.
__global__ void scan_kernel(int n) {
    __shared__ int ssum[SCAN_T];
    int tid = threadIdx.x;
    int chunk = (n + SCAN_T - 1) / SCAN_T;
    int begin = tid * chunk;
    int end   = begin + chunk; if (end > n) end = n;
    int s = 0;
    for (int i = begin; i < end; i++) s += g_cnt[i] - 1;
    ssum[tid] = s;
    __syncthreads();
    // Hillis-Steele inclusive scan
    for (int d = 1; d < SCAN_T; d <<= 1) {
        int v = (tid >= d) ? ssum[tid - d] : 0;
        __syncthreads();
        ssum[tid] += v;
        __syncthreads();
    }
    int off = (tid == 0) ? 0 : ssum[tid - 1];
    for (int i = begin; i < end; i++) {
        g_rowptr[i] = off;
        g_cur[i]    = off;
        off += g_cnt[i] - 1;
    }
}

// Bucket edges by dst into CSC.
__global__ void bucket_kernel(int E) {
    int e = blockIdx.x * blockDim.x + threadIdx.x;
    if (e < E) {
        int2 sd = g_edge[e];
        int pos = atomicAdd(&g_cur[sd.y], 1);
        g_csrc[pos] = sd.x;
    }
}

// Atomic-free pull filter: 16 lanes per dst node (one 16B quad each).
// sel: 0 -> read g_zA, 1 -> read g_zB.  Writes g_zf.
__global__ __launch_bounds__(256)
void filter_kernel(int n, int sel) {
    int t = blockIdx.x * blockDim.x + threadIdx.x;
    int node = t >> 4;
    int q    = t & 15;
    if (node >= n) return;
    const float* z = sel ? g_zB : g_zA;

    int start = g_rowptr[node];
    int cnt   = g_cnt[node];          // indeg+1
    int end   = start + cnt - 1;

    float4 s0 = make_float4(0.f, 0.f, 0.f, 0.f);
    float4 s1 = make_float4(0.f, 0.f, 0.f, 0.f);
    int j = start;
    for (; j + 1 < end; j += 2) {
        int a = __ldg(&g_csrc[j]);
        int b = __ldg(&g_csrc[j + 1]);
        float4 va = *reinterpret_cast<const float4*>(z + (size_t)a * D + q * 4);
        float4 vb = *reinterpret_cast<const float4*>(z + (size_t)b * D + q * 4);
        s0.x += va.x; s0.y += va.y; s0.z += va.z; s0.w += va.w;
        s1.x += vb.x; s1.y += vb.y; s1.z += vb.z; s1.w += vb.w;
    }
    if (j < end) {
        int a = __ldg(&g_csrc[j]);
        float4 va = *reinterpret_cast<const float4*>(z + (size_t)a * D + q * 4);
        s0.x += va.x; s0.y += va.y; s0.z += va.z; s0.w += va.w;
    }
    float4 sum = make_float4(s0.x + s1.x, s0.y + s1.y, s0.z + s1.z, s0.w + s1.w);

    float inv = 1.0f / ((float)g_deg[node] * (float)cnt);
    float om  = 1.0f - inv;
    float4 zv = *reinterpret_cast<const float4*>(z + (size_t)node * D + q * 4);
    float4 o;
    o.x = zv.x * om - sum.x * inv;
    o.y = zv.y * om - sum.y * inv;
    o.z = zv.z * om - sum.z * inv;
    o.w = zv.w * om - sum.w * inv;
    *reinterpret_cast<float4*>(g_zf + (size_t)node * D + q * 4) = o;
}

// ---------------------------------------------------------------------------
// Tiled GEMM: out = relu(X @ W + b)
// stage 0: X = Xext, out = g_zA
// stage 1: X = g_zf, out = g_zB
// stage 2: X = g_zf, out = Oext
// 256 threads, 64 rows/block; each thread: 4 rows x 4 cols; x loaded as
// float4 over k -> 8 LDS.128 per 4 k-steps (was 20 LDS ops).
// ---------------------------------------------------------------------------
__global__ __launch_bounds__(256, 4)
void gemm_relu_kernel(const float* __restrict__ Xext,
                      float* __restrict__ Oext,
                      const float* __restrict__ W,
                      const float* __restrict__ B,
                      int n, int stage) {
    __shared__ float Ws[D * D];
    __shared__ float xs[64 * D];
    const int tid = threadIdx.x;
    const int r0  = blockIdx.x * 64;

    const float* X   = (stage == 0) ? Xext : g_zf;
    float*       out = (stage == 0) ? g_zA : (stage == 1 ? g_zB : Oext);

    {
        const float4* Wv  = reinterpret_cast<const float4*>(W);
        float4*       Wsv = reinterpret_cast<float4*>(Ws);
#pragma unroll
        for (int i = 0; i < 4; i++) Wsv[tid + 256 * i] = Wv[tid + 256 * i];
    }
#pragma unroll
    for (int i = 0; i < 4; i++) {
        int idx  = tid + 256 * i;
        int row  = idx >> 4;
        int qc   = idx & 15;
        int grow = r0 + row;
        float4 v = make_float4(0.f, 0.f, 0.f, 0.f);
        if (grow < n)
            v = *reinterpret_cast<const float4*>(X + (size_t)grow * D + qc * 4);
        *reinterpret_cast<float4*>(xs + row * D + qc * 4) = v;
    }
    __syncthreads();

    const int jj = tid & 15;   // column quad
    const int ty = tid >> 4;   // row base
    float4 acc4[4];
#pragma unroll
    for (int r = 0; r < 4; r++) acc4[r] = make_float4(0.f, 0.f, 0.f, 0.f);

#pragma unroll 4
    for (int k0 = 0; k0 < D; k0 += 4) {
        float4 xv[4];
#pragma unroll
        for (int r = 0; r < 4; r++)
            xv[r] = *reinterpret_cast<const float4*>(&xs[(ty + 16 * r) * D + k0]);
#pragma unroll
        for (int kk = 0; kk < 4; kk++) {
            float4 w = *reinterpret_cast<const float4*>(&Ws[(k0 + kk) * D + jj * 4]);
#pragma unroll
            for (int r = 0; r < 4; r++) {
                float xk = (kk == 0) ? xv[r].x : (kk == 1) ? xv[r].y
                         : (kk == 2) ? xv[r].z : xv[r].w;
                acc4[r].x = fmaf(xk, w.x, acc4[r].x);
                acc4[r].y = fmaf(xk, w.y, acc4[r].y);
                acc4[r].z = fmaf(xk, w.z, acc4[r].z);
                acc4[r].w = fmaf(xk, w.w, acc4[r].w);
            }
        }
    }

    float4 bj = *reinterpret_cast<const float4*>(B + jj * 4);
#pragma unroll
    for (int r = 0; r < 4; r++) {
        int grow = r0 + ty + 16 * r;
        if (grow < n) {
            float4 o;
            o.x = fmaxf(acc4[r].x + bj.x, 0.f);
            o.y = fmaxf(acc4[r].y + bj.y, 0.f);
            o.z = fmaxf(acc4[r].z + bj.z, 0.f);
            o.w = fmaxf(acc4[r].w + bj.w, 0.f);
            *reinterpret_cast<float4*>(out + (size_t)grow * D + jj * 4) = o;
        }
    }
}

// ---------------------------------------------------------------------------
extern "C" void kernel_launch(void* const* d_in, const int* in_sizes, int n_in,
                              void* d_out, int out_size) {
    // Bind inputs by element count (robust to ordering), positional fallback.
    int ix = -1, ie = -1, iW[3] = {-1, -1, -1}, ib[3] = {-1, -1, -1};
    int nW = 0, nb = 0;
    for (int i = 0; i < n_in; i++) {
        int s = in_sizes[i];
        if (s == N_NODES * D)          ix = i;
        else if (s == 2 * N_EDGES)     ie = i;
        else if (s == D * D && nW < 3) iW[nW++] = i;
        else if (s == D && nb < 3)     ib[nb++] = i;
    }
    if (ix < 0 || ie < 0 || nW < 3 || nb < 3) {
        ix = 0; ie = 1;
        iW[0] = 2; ib[0] = 3; iW[1] = 4; ib[1] = 5; iW[2] = 6; ib[2] = 7;
    }

    const float* x  = (const float*)d_in[ix];
    const void*  ei = d_in[ie];
    const float* W1 = (const float*)d_in[iW[0]];
    const float* b1 = (const float*)d_in[ib[0]];
    const float* W2 = (const float*)d_in[iW[1]];
    const float* b2 = (const float*)d_in[ib[1]];
    const float* W3 = (const float*)d_in[iW[2]];
    const float* b3 = (const float*)d_in[ib[2]];
    float* out = (float*)d_out;

    const int n = in_sizes[ix] / D;      // 100000
    const int E = in_sizes[ie] / 2;      // 1200000

    const int gemm_blocks   = (n + 63) / 64;
    const int filter_blocks = (n * 16 + 255) / 256;

    // graph prep: dtype probe, degree counts, decode, CSC build
    detect_dtype_kernel<<<1, 32>>>((const long long*)ei);
    init_counts_kernel<<<(n + 255) / 256, 256>>>(n);
    edge_prep_kernel<<<(E + 255) / 256, 256>>>(ei, E, n);

    // layer 1: x -> g_zA (independent of CSC build)
    gemm_relu_kernel<<<gemm_blocks, 256>>>(x, nullptr, W1, b1, n, 0);

    scan_kernel<<<1, SCAN_T>>>(n);
    bucket_kernel<<<(E + 255) / 256, 256>>>(E);

    // filter 1: g_zA -> g_zf (pull, atomic-free)
    filter_kernel<<<filter_blocks, 256>>>(n, 0);

    // layer 2: g_zf -> g_zB
    gemm_relu_kernel<<<gemm_blocks, 256>>>(nullptr, nullptr, W2, b2, n, 1);

    // filter 2: g_zB -> g_zf
    filter_kernel<<<filter_blocks, 256>>>(n, 1);

    // layer 3: g_zf -> d_out
    gemm_relu_kernel<<<gemm_blocks, 256>>>(nullptr, out, W3, b3, n, 2);
}

// round 12
// speedup vs baseline: 1.8225x; 1.8225x over previous
#include <cuda_runtime.h>
#include <cuda_bf16.h>
#include <cstdint>

// ---------------------------------------------------------------------------
// SupGCL_GConv: 3x [GEMM(64x64)+bias+relu] interleaved with 2x high-pass
// graph filter:  out = z*(1-inv) - (sum_{j->i} z[j])*inv,  inv = 1/(deg*cnt)
//   deg[i] = outdeg(i)+1, cnt[i] = indeg(i)+1  (self loops folded in algebra)
//
// R9: pull/CSC filter kept (307MB coalesced gather + 25.6MB write per filter,
// no atomic RMW), but prep parallelized:
//   - 3-kernel coalesced scan (partials -> scan partials -> fill) replaces the
//     single-block chunk-strided scan that caused the R7 regression
//   - g_edge scratch removed; bucket re-decodes indices directly
//   - filter gathers unrolled 4x (4 independent accumulators, MLP=4)
// ---------------------------------------------------------------------------

#define N_NODES 100000
#define D 64
#define N_EDGES 1200000
#define NBMAX 512     // >= ceil(N_NODES/256) = 391

__device__ __align__(16) float g_zA[(size_t)N_NODES * D];   // gemm1 out
__device__ __align__(16) float g_zB[(size_t)N_NODES * D];   // gemm2 out
__device__ __align__(16) float g_zf[(size_t)N_NODES * D];   // filtered z
__device__ int g_csrc[N_EDGES];     // CSC: src id per dst-sorted slot
__device__ int g_rowptr[N_NODES];   // CSC row starts
__device__ int g_cur[N_NODES];      // bucket cursors
__device__ int g_deg[N_NODES];      // outdeg+1
__device__ int g_cnt[N_NODES];      // indeg+1
__device__ int g_part[NBMAX];       // scan partials
__device__ int g_is64;

// ---------------------------------------------------------------------------
__global__ void detect_dtype_kernel(const long long* __restrict__ ei) {
    // int64 buffer -> first 8 values are valid node ids; int32 viewed as int64
    // packs two ids -> >= 2^32 w.h.p.
    if (blockIdx.x == 0 && threadIdx.x == 0) {
        bool ok = true;
        for (int i = 0; i < 8; i++) {
            long long v = ei[i];
            if (v < 0 || v >= N_NODES) ok = false;
        }
        g_is64 = ok ? 1 : 0;
    }
}

__global__ void init_counts_kernel(int n) {
    int i = blockIdx.x * blockDim.x + threadIdx.x;
    if (i < n) { g_deg[i] = 1; g_cnt[i] = 1; }   // self loops
}

// Count degrees only (no edge materialization).
__global__ void edge_prep_kernel(const void* __restrict__ ei, int E, int n) {
    int e = blockIdx.x * blockDim.x + threadIdx.x;
    if (e >= E) return;
    int s, t;
    if (g_is64) {
        s = (int)((const long long*)ei)[e];
        t = (int)((const long long*)ei)[E + e];
    } else {
        s = ((const int*)ei)[e];
        t = ((const int*)ei)[E + e];
    }
    if ((unsigned)s >= (unsigned)n) s = 0;   // defensive: wrong beats crash
    if ((unsigned)t >= (unsigned)n) t = 0;
    atomicAdd(&g_deg[s], 1);
    atomicAdd(&g_cnt[t], 1);
}

// ---- parallel exclusive scan of indeg (= cnt-1) -> rowptr, cur ------------
__global__ void scan_partial_kernel(int n) {
    __shared__ int sh[256];
    int i = blockIdx.x * 256 + threadIdx.x;
    sh[threadIdx.x] = (i < n) ? (g_cnt[i] - 1) : 0;
    __syncthreads();
#pragma unroll
    for (int d = 128; d > 0; d >>= 1) {
        if (threadIdx.x < d) sh[threadIdx.x] += sh[threadIdx.x + d];
        __syncthreads();
    }
    if (threadIdx.x == 0) g_part[blockIdx.x] = sh[0];
}

__global__ void scan_bases_kernel(int nb) {
    __shared__ int sh[NBMAX];
    int tid = threadIdx.x;
    int v = (tid < nb) ? g_part[tid] : 0;
    sh[tid] = v;
    __syncthreads();
    for (int d = 1; d < NBMAX; d <<= 1) {
        int u = (tid >= d) ? sh[tid - d] : 0;
        __syncthreads();
        sh[tid] += u;
        __syncthreads();
    }
    if (tid < nb) g_part[tid] = sh[tid] - v;   // exclusive base per block
}

__global__ void scan_fill_kernel(int n) {
    __shared__ int sh[256];
    int tid = threadIdx.x;
    int i = blockIdx.x * 256 + tid;
    int v = (i < n) ? (g_cnt[i] - 1) : 0;
    sh[tid] = v;
    __syncthreads();
    for (int d = 1; d < 256; d <<= 1) {
        int u = (tid >= d) ? sh[tid - d] : 0;
        __syncthreads();
        sh[tid] += u;
        __syncthreads();
    }
    if (i < n) {
        int off = g_part[blockIdx.x] + sh[tid] - v;   // exclusive
        g_rowptr[i] = off;
        g_cur[i]    = off;
    }
}

// Bucket edges by dst into CSC (re-decodes indices from the input buffer).
__global__ void bucket_kernel(const void* __restrict__ ei, int E, int n) {
    int e = blockIdx.x * blockDim.x + threadIdx.x;
    if (e >= E) return;
    int s, t;
    if (g_is64) {
        s = (int)((const long long*)ei)[e];
        t = (int)((const long long*)ei)[E + e];
    } else {
        s = ((const int*)ei)[e];
        t = ((const int*)ei)[E + e];
    }
    if ((unsigned)s >= (unsigned)n) s = 0;
    if ((unsigned)t >= (unsigned)n) t = 0;
    int pos = atomicAdd(&g_cur[t], 1);
    g_csrc[pos] = s;
}

// Atomic-free pull filter: 16 lanes per dst node (one 16B quad each).
// sel: 0 -> read g_zA, 1 -> read g_zB.  Writes g_zf.
__global__ __launch_bounds__(256)
void filter_kernel(int n, int sel) {
    int t = blockIdx.x * blockDim.x + threadIdx.x;
    int node = t >> 4;
    int q    = t & 15;
    if (node >= n) return;
    const float* z = sel ? g_zB : g_zA;

    int start = g_rowptr[node];
    int cnt   = g_cnt[node];          // indeg+1
    int end   = start + cnt - 1;

    float4 s0 = make_float4(0.f, 0.f, 0.f, 0.f);
    float4 s1 = make_float4(0.f, 0.f, 0.f, 0.f);
    float4 s2 = make_float4(0.f, 0.f, 0.f, 0.f);
    float4 s3 = make_float4(0.f, 0.f, 0.f, 0.f);
    int j = start;
    for (; j + 3 < end; j += 4) {
        int a0 = __ldg(&g_csrc[j]);
        int a1 = __ldg(&g_csrc[j + 1]);
        int a2 = __ldg(&g_csrc[j + 2]);
        int a3 = __ldg(&g_csrc[j + 3]);
        float4 v0 = *reinterpret_cast<const float4*>(z + (size_t)a0 * D + q * 4);
        float4 v1 = *reinterpret_cast<const float4*>(z + (size_t)a1 * D + q * 4);
        float4 v2 = *reinterpret_cast<const float4*>(z + (size_t)a2 * D + q * 4);
        float4 v3 = *reinterpret_cast<const float4*>(z + (size_t)a3 * D + q * 4);
        s0.x += v0.x; s0.y += v0.y; s0.z += v0.z; s0.w += v0.w;
        s1.x += v1.x; s1.y += v1.y; s1.z += v1.z; s1.w += v1.w;
        s2.x += v2.x; s2.y += v2.y; s2.z += v2.z; s2.w += v2.w;
        s3.x += v3.x; s3.y += v3.y; s3.z += v3.z; s3.w += v3.w;
    }
    for (; j < end; j++) {
        int a = __ldg(&g_csrc[j]);
        float4 v = *reinterpret_cast<const float4*>(z + (size_t)a * D + q * 4);
        s0.x += v.x; s0.y += v.y; s0.z += v.z; s0.w += v.w;
    }
    float4 sum;
    sum.x = (s0.x + s1.x) + (s2.x + s3.x);
    sum.y = (s0.y + s1.y) + (s2.y + s3.y);
    sum.z = (s0.z + s1.z) + (s2.z + s3.z);
    sum.w = (s0.w + s1.w) + (s2.w + s3.w);

    float inv = 1.0f / ((float)g_deg[node] * (float)cnt);
    float om  = 1.0f - inv;
    float4 zv = *reinterpret_cast<const float4*>(z + (size_t)node * D + q * 4);
    float4 o;
    o.x = zv.x * om - sum.x * inv;
    o.y = zv.y * om - sum.y * inv;
    o.z = zv.z * om - sum.z * inv;
    o.w = zv.w * om - sum.w * inv;
    *reinterpret_cast<float4*>(g_zf + (size_t)node * D + q * 4) = o;
}

// ---------------------------------------------------------------------------
// Tiled GEMM: out = relu(X @ W + b)
// stage 0: X = Xext, out = g_zA
// stage 1: X = g_zf, out = g_zB
// stage 2: X = g_zf, out = Oext
// 256 threads, 64 rows/block; each thread: 4 rows x 4 cols.
// ---------------------------------------------------------------------------
__global__ __launch_bounds__(256, 4)
void gemm_relu_kernel(const float* __restrict__ Xext,
                      float* __restrict__ Oext,
                      const float* __restrict__ W,
                      const float* __restrict__ B,
                      int n, int stage) {
    __shared__ float Ws[D * D];
    __shared__ float xs[64 * D];
    const int tid = threadIdx.x;
    const int r0  = blockIdx.x * 64;

    const float* X   = (stage == 0) ? Xext : g_zf;
    float*       out = (stage == 0) ? g_zA : (stage == 1 ? g_zB : Oext);

    {
        const float4* Wv  = reinterpret_cast<const float4*>(W);
        float4*       Wsv = reinterpret_cast<float4*>(Ws);
#pragma unroll
        for (int i = 0; i < 4; i++) Wsv[tid + 256 * i] = Wv[tid + 256 * i];
    }
#pragma unroll
    for (int i = 0; i < 4; i++) {
        int idx  = tid + 256 * i;
        int row  = idx >> 4;
        int qc   = idx & 15;
        int grow = r0 + row;
        float4 v = make_float4(0.f, 0.f, 0.f, 0.f);
        if (grow < n)
            v = *reinterpret_cast<const float4*>(X + (size_t)grow * D + qc * 4);
        *reinterpret_cast<float4*>(xs + row * D + qc * 4) = v;
    }
    __syncthreads();

    const int jj = tid & 15;   // column quad
    const int ty = tid >> 4;   // row base
    float4 acc4[4];
#pragma unroll
    for (int r = 0; r < 4; r++) acc4[r] = make_float4(0.f, 0.f, 0.f, 0.f);

#pragma unroll 4
    for (int k0 = 0; k0 < D; k0 += 4) {
        float4 xv[4];
#pragma unroll
        for (int r = 0; r < 4; r++)
            xv[r] = *reinterpret_cast<const float4*>(&xs[(ty + 16 * r) * D + k0]);
#pragma unroll
        for (int kk = 0; kk < 4; kk++) {
            float4 w = *reinterpret_cast<const float4*>(&Ws[(k0 + kk) * D + jj * 4]);
#pragma unroll
            for (int r = 0; r < 4; r++) {
                float xk = (kk == 0) ? xv[r].x : (kk == 1) ? xv[r].y
                         : (kk == 2) ? xv[r].z : xv[r].w;
                acc4[r].x = fmaf(xk, w.x, acc4[r].x);
                acc4[r].y = fmaf(xk, w.y, acc4[r].y);
                acc4[r].z = fmaf(xk, w.z, acc4[r].z);
                acc4[r].w = fmaf(xk, w.w, acc4[r].w);
            }
        }
    }

    float4 bj = *reinterpret_cast<const float4*>(B + jj * 4);
#pragma unroll
    for (int r = 0; r < 4; r++) {
        int grow = r0 + ty + 16 * r;
        if (grow < n) {
            float4 o;
            o.x = fmaxf(acc4[r].x + bj.x, 0.f);
            o.y = fmaxf(acc4[r].y + bj.y, 0.f);
            o.z = fmaxf(acc4[r].z + bj.z, 0.f);
            o.w = fmaxf(acc4[r].w + bj.w, 0.f);
            *reinterpret_cast<float4*>(out + (size_t)grow * D + jj * 4) = o;
        }
    }
}

// ---------------------------------------------------------------------------
extern "C" void kernel_launch(void* const* d_in, const int* in_sizes, int n_in,
                              void* d_out, int out_size) {
    // Bind inputs by element count (robust to ordering), positional fallback.
    int ix = -1, ie = -1, iW[3] = {-1, -1, -1}, ib[3] = {-1, -1, -1};
    int nW = 0, nb = 0;
    for (int i = 0; i < n_in; i++) {
        int s = in_sizes[i];
        if (s == N_NODES * D)          ix = i;
        else if (s == 2 * N_EDGES)     ie = i;
        else if (s == D * D && nW < 3) iW[nW++] = i;
        else if (s == D && nb < 3)     ib[nb++] = i;
    }
    if (ix < 0 || ie < 0 || nW < 3 || nb < 3) {
        ix = 0; ie = 1;
        iW[0] = 2; ib[0] = 3; iW[1] = 4; ib[1] = 5; iW[2] = 6; ib[2] = 7;
    }

    const float* x  = (const float*)d_in[ix];
    const void*  ei = d_in[ie];
    const float* W1 = (const float*)d_in[iW[0]];
    const float* b1 = (const float*)d_in[ib[0]];
    const float* W2 = (const float*)d_in[iW[1]];
    const float* b2 = (const float*)d_in[ib[1]];
    const float* W3 = (const float*)d_in[iW[2]];
    const float* b3 = (const float*)d_in[ib[2]];
    float* out = (float*)d_out;

    const int n = in_sizes[ix] / D;      // 100000
    const int E = in_sizes[ie] / 2;      // 1200000

    const int gemm_blocks   = (n + 63) / 64;
    const int filter_blocks = (n * 16 + 255) / 256;
    const int node_blocks   = (n + 255) / 256;   // = NB for the scan

    // graph prep: dtype probe, degree counts
    detect_dtype_kernel<<<1, 32>>>((const long long*)ei);
    init_counts_kernel<<<node_blocks, 256>>>(n);
    edge_prep_kernel<<<(E + 255) / 256, 256>>>(ei, E, n);

    // layer 1: x -> g_zA (independent of CSC build, overlaps nothing serially
    // but keeps the GPU busy between prep phases in graph replay)
    gemm_relu_kernel<<<gemm_blocks, 256>>>(x, nullptr, W1, b1, n, 0);

    // CSC build: parallel scan + bucket
    scan_partial_kernel<<<node_blocks, 256>>>(n);
    scan_bases_kernel<<<1, NBMAX>>>(node_blocks);
    scan_fill_kernel<<<node_blocks, 256>>>(n);
    bucket_kernel<<<(E + 255) / 256, 256>>>(ei, E, n);

    // filter 1: g_zA -> g_zf (pull, atomic-free)
    filter_kernel<<<filter_blocks, 256>>>(n, 0);

    // layer 2: g_zf -> g_zB
    gemm_relu_kernel<<<gemm_blocks, 256>>>(nullptr, nullptr, W2, b2, n, 1);

    // filter 2: g_zB -> g_zf
    filter_kernel<<<filter_blocks, 256>>>(n, 1);

    // layer 3: g_zf -> d_out
    gemm_relu_kernel<<<gemm_blocks, 256>>>(nullptr, out, W3, b3, n, 2);
}

// round 13
// speedup vs baseline: 1.8271x; 1.0025x over previous
#include <cuda_runtime.h>
#include <cuda_bf16.h>
#include <cstdint>

// ---------------------------------------------------------------------------
// SupGCL_GConv: 3x [GEMM(64x64)+bias+relu] interleaved with 2x high-pass
// graph filter:  out = z*(1-inv) - (sum_{j->i} z[j])*inv,  inv = 1/(deg*cnt)
//   deg[i] = outdeg(i)+1, cnt[i] = indeg(i)+1  (self loops folded in algebra)
//
// R12: GEMM rewritten around sm_103a packed fp32 FMA (fma.rn.f32x2 -> FFMA2),
// halving the FFMA issue count that was the measured floor (82% of scalar
// FFMA ceiling). 8x8 register blocking (128 thr/block, 128-row tile) cuts
// smem traffic to ~1 B/FMA so smem doesn't become the new binder; bias is
// pre-packed into the f32x2 accumulators; xs rows padded +16B to avoid the
// 256B-stride 4-way bank conflict. Filter/prep identical to the R9 winner.
// ---------------------------------------------------------------------------

#define N_NODES 100000
#define D 64
#define N_EDGES 1200000
#define NBMAX 512     // >= ceil(N_NODES/256) = 391
#define GR 128        // gemm rows per block
#define XPAD 4        // xs row padding (floats)

__device__ __align__(16) float g_zA[(size_t)N_NODES * D];   // gemm1 out
__device__ __align__(16) float g_zB[(size_t)N_NODES * D];   // gemm2 out
__device__ __align__(16) float g_zf[(size_t)N_NODES * D];   // filtered z
__device__ int g_csrc[N_EDGES];     // CSC: src id per dst-sorted slot
__device__ int g_rowptr[N_NODES];   // CSC row starts
__device__ int g_cur[N_NODES];      // bucket cursors
__device__ int g_deg[N_NODES];      // outdeg+1
__device__ int g_cnt[N_NODES];      // indeg+1
__device__ int g_part[NBMAX];       // scan partials
__device__ int g_is64;

// ---------------------------------------------------------------------------
__global__ void detect_dtype_kernel(const long long* __restrict__ ei) {
    // int64 buffer -> first 8 values are valid node ids; int32 viewed as int64
    // packs two ids -> >= 2^32 w.h.p.
    if (blockIdx.x == 0 && threadIdx.x == 0) {
        bool ok = true;
        for (int i = 0; i < 8; i++) {
            long long v = ei[i];
            if (v < 0 || v >= N_NODES) ok = false;
        }
        g_is64 = ok ? 1 : 0;
    }
}

__global__ void init_counts_kernel(int n) {
    int i = blockIdx.x * blockDim.x + threadIdx.x;
    if (i < n) { g_deg[i] = 1; g_cnt[i] = 1; }   // self loops
}

// Count degrees only (no edge materialization).
__global__ void edge_prep_kernel(const void* __restrict__ ei, int E, int n) {
    int e = blockIdx.x * blockDim.x + threadIdx.x;
    if (e >= E) return;
    int s, t;
    if (g_is64) {
        s = (int)((const long long*)ei)[e];
        t = (int)((const long long*)ei)[E + e];
    } else {
        s = ((const int*)ei)[e];
        t = ((const int*)ei)[E + e];
    }
    if ((unsigned)s >= (unsigned)n) s = 0;   // defensive: wrong beats crash
    if ((unsigned)t >= (unsigned)n) t = 0;
    atomicAdd(&g_deg[s], 1);
    atomicAdd(&g_cnt[t], 1);
}

// ---- parallel exclusive scan of indeg (= cnt-1) -> rowptr, cur ------------
__global__ void scan_partial_kernel(int n) {
    __shared__ int sh[256];
    int i = blockIdx.x * 256 + threadIdx.x;
    sh[threadIdx.x] = (i < n) ? (g_cnt[i] - 1) : 0;
    __syncthreads();
#pragma unroll
    for (int d = 128; d > 0; d >>= 1) {
        if (threadIdx.x < d) sh[threadIdx.x] += sh[threadIdx.x + d];
        __syncthreads();
    }
    if (threadIdx.x == 0) g_part[blockIdx.x] = sh[0];
}

__global__ void scan_bases_kernel(int nb) {
    __shared__ int sh[NBMAX];
    int tid = threadIdx.x;
    int v = (tid < nb) ? g_part[tid] : 0;
    sh[tid] = v;
    __syncthreads();
    for (int d = 1; d < NBMAX; d <<= 1) {
        int u = (tid >= d) ? sh[tid - d] : 0;
        __syncthreads();
        sh[tid] += u;
        __syncthreads();
    }
    if (tid < nb) g_part[tid] = sh[tid] - v;   // exclusive base per block
}

__global__ void scan_fill_kernel(int n) {
    __shared__ int sh[256];
    int tid = threadIdx.x;
    int i = blockIdx.x * 256 + tid;
    int v = (i < n) ? (g_cnt[i] - 1) : 0;
    sh[tid] = v;
    __syncthreads();
    for (int d = 1; d < 256; d <<= 1) {
        int u = (tid >= d) ? sh[tid - d] : 0;
        __syncthreads();
        sh[tid] += u;
        __syncthreads();
    }
    if (i < n) {
        int off = g_part[blockIdx.x] + sh[tid] - v;   // exclusive
        g_rowptr[i] = off;
        g_cur[i]    = off;
    }
}

// Bucket edges by dst into CSC (re-decodes indices from the input buffer).
__global__ void bucket_kernel(const void* __restrict__ ei, int E, int n) {
    int e = blockIdx.x * blockDim.x + threadIdx.x;
    if (e >= E) return;
    int s, t;
    if (g_is64) {
        s = (int)((const long long*)ei)[e];
        t = (int)((const long long*)ei)[E + e];
    } else {
        s = ((const int*)ei)[e];
        t = ((const int*)ei)[E + e];
    }
    if ((unsigned)s >= (unsigned)n) s = 0;
    if ((unsigned)t >= (unsigned)n) t = 0;
    int pos = atomicAdd(&g_cur[t], 1);
    g_csrc[pos] = s;
}

// Atomic-free pull filter: 16 lanes per dst node (one 16B quad each).
// sel: 0 -> read g_zA, 1 -> read g_zB.  Writes g_zf.
__global__ __launch_bounds__(256)
void filter_kernel(int n, int sel) {
    int t = blockIdx.x * blockDim.x + threadIdx.x;
    int node = t >> 4;
    int q    = t & 15;
    if (node >= n) return;
    const float* z = sel ? g_zB : g_zA;

    int start = g_rowptr[node];
    int cnt   = g_cnt[node];          // indeg+1
    int end   = start + cnt - 1;

    float4 s0 = make_float4(0.f, 0.f, 0.f, 0.f);
    float4 s1 = make_float4(0.f, 0.f, 0.f, 0.f);
    float4 s2 = make_float4(0.f, 0.f, 0.f, 0.f);
    float4 s3 = make_float4(0.f, 0.f, 0.f, 0.f);
    int j = start;
    for (; j + 3 < end; j += 4) {
        int a0 = __ldg(&g_csrc[j]);
        int a1 = __ldg(&g_csrc[j + 1]);
        int a2 = __ldg(&g_csrc[j + 2]);
        int a3 = __ldg(&g_csrc[j + 3]);
        float4 v0 = *reinterpret_cast<const float4*>(z + (size_t)a0 * D + q * 4);
        float4 v1 = *reinterpret_cast<const float4*>(z + (size_t)a1 * D + q * 4);
        float4 v2 = *reinterpret_cast<const float4*>(z + (size_t)a2 * D + q * 4);
        float4 v3 = *reinterpret_cast<const float4*>(z + (size_t)a3 * D + q * 4);
        s0.x += v0.x; s0.y += v0.y; s0.z += v0.z; s0.w += v0.w;
        s1.x += v1.x; s1.y += v1.y; s1.z += v1.z; s1.w += v1.w;
        s2.x += v2.x; s2.y += v2.y; s2.z += v2.z; s2.w += v2.w;
        s3.x += v3.x; s3.y += v3.y; s3.z += v3.z; s3.w += v3.w;
    }
    for (; j < end; j++) {
        int a = __ldg(&g_csrc[j]);
        float4 v = *reinterpret_cast<const float4*>(z + (size_t)a * D + q * 4);
        s0.x += v.x; s0.y += v.y; s0.z += v.z; s0.w += v.w;
    }
    float4 sum;
    sum.x = (s0.x + s1.x) + (s2.x + s3.x);
    sum.y = (s0.y + s1.y) + (s2.y + s3.y);
    sum.z = (s0.z + s1.z) + (s2.z + s3.z);
    sum.w = (s0.w + s1.w) + (s2.w + s3.w);

    float inv = 1.0f / ((float)g_deg[node] * (float)cnt);
    float om  = 1.0f - inv;
    float4 zv = *reinterpret_cast<const float4*>(z + (size_t)node * D + q * 4);
    float4 o;
    o.x = zv.x * om - sum.x * inv;
    o.y = zv.y * om - sum.y * inv;
    o.z = zv.z * om - sum.z * inv;
    o.w = zv.w * om - sum.w * inv;
    *reinterpret_cast<float4*>(g_zf + (size_t)node * D + q * 4) = o;
}

// ---------------------------------------------------------------------------
// FFMA2 GEMM: out = relu(X @ W + b)
// stage 0: X = Xext, out = g_zA ; stage 1: X = g_zf, out = g_zB ;
// stage 2: X = g_zf, out = Oext
// 128 threads/block, 128-row tile. Thread (cg = tid&7, rg = tid>>3):
//   cols 8*cg..8*cg+7 (4 f32x2 pairs), rows rg + 16*r, r = 0..7.
// Accumulators live as packed f32x2 (init = bias), inner loop is
// fma.rn.f32x2 -> FFMA2 (2 FMAs / instr / lane).
// ---------------------------------------------------------------------------
__global__ __launch_bounds__(128)
void gemm_relu_kernel(const float* __restrict__ Xext,
                      float* __restrict__ Oext,
                      const float* __restrict__ W,
                      const float* __restrict__ B,
                      int n, int stage) {
    __shared__ float Ws[D * D];
    __shared__ float xs[GR * (D + XPAD)];
    const int tid = threadIdx.x;
    const int r0  = blockIdx.x * GR;
    const int XS  = D + XPAD;

    const float* X   = (stage == 0) ? Xext : g_zf;
    float*       out = (stage == 0) ? g_zA : (stage == 1 ? g_zB : Oext);

    // load W (4096 floats = 1024 float4), 8 per thread
    {
        const float4* Wv  = reinterpret_cast<const float4*>(W);
        float4*       Wsv = reinterpret_cast<float4*>(Ws);
#pragma unroll
        for (int i = 0; i < 8; i++) Wsv[tid + 128 * i] = Wv[tid + 128 * i];
    }
    // load 128x64 x tile (2048 float4), 16 per thread
#pragma unroll
    for (int i = 0; i < 16; i++) {
        int idx  = tid + 128 * i;
        int row  = idx >> 4;
        int qc   = idx & 15;
        int grow = r0 + row;
        float4 v = make_float4(0.f, 0.f, 0.f, 0.f);
        if (grow < n)
            v = *reinterpret_cast<const float4*>(X + (size_t)grow * D + qc * 4);
        *reinterpret_cast<float4*>(xs + row * XS + qc * 4) = v;
    }
    __syncthreads();

    const int cg = tid & 7;    // col group: cols 8*cg .. 8*cg+7
    const int rg = tid >> 3;   // row base: rows rg + 16*r

    // accumulators = packed f32x2 pairs, pre-loaded with bias
    unsigned long long acc[8][4];
    {
        const double2* bv = reinterpret_cast<const double2*>(B + cg * 8);
        double2 ba = bv[0], bb = bv[1];
        unsigned long long bp0 = __double_as_longlong(ba.x);
        unsigned long long bp1 = __double_as_longlong(ba.y);
        unsigned long long bp2 = __double_as_longlong(bb.x);
        unsigned long long bp3 = __double_as_longlong(bb.y);
#pragma unroll
        for (int r = 0; r < 8; r++) {
            acc[r][0] = bp0; acc[r][1] = bp1; acc[r][2] = bp2; acc[r][3] = bp3;
        }
    }

#pragma unroll 4
    for (int k0 = 0; k0 < D; k0 += 4) {
        float4 xr[8];
#pragma unroll
        for (int r = 0; r < 8; r++)
            xr[r] = *reinterpret_cast<const float4*>(&xs[(rg + 16 * r) * XS + k0]);
#pragma unroll
        for (int kk = 0; kk < 4; kk++) {
            const double2* wp =
                reinterpret_cast<const double2*>(&Ws[(k0 + kk) * D + cg * 8]);
            double2 wa = wp[0], wb = wp[1];
            unsigned long long w0 = __double_as_longlong(wa.x);
            unsigned long long w1 = __double_as_longlong(wa.y);
            unsigned long long w2 = __double_as_longlong(wb.x);
            unsigned long long w3 = __double_as_longlong(wb.y);
#pragma unroll
            for (int r = 0; r < 8; r++) {
                float xv = (kk == 0) ? xr[r].x : (kk == 1) ? xr[r].y
                         : (kk == 2) ? xr[r].z : xr[r].w;
                unsigned long long xx;
                asm("mov.b64 %0, {%1, %1};" : "=l"(xx) : "f"(xv));
                asm("fma.rn.f32x2 %0, %1, %2, %0;" : "+l"(acc[r][0]) : "l"(xx), "l"(w0));
                asm("fma.rn.f32x2 %0, %1, %2, %0;" : "+l"(acc[r][1]) : "l"(xx), "l"(w1));
                asm("fma.rn.f32x2 %0, %1, %2, %0;" : "+l"(acc[r][2]) : "l"(xx), "l"(w2));
                asm("fma.rn.f32x2 %0, %1, %2, %0;" : "+l"(acc[r][3]) : "l"(xx), "l"(w3));
            }
        }
    }

    // epilogue: unpack, relu, store 32B per row
#pragma unroll
    for (int r = 0; r < 8; r++) {
        int grow = r0 + rg + 16 * r;
        if (grow < n) {
            float lo[4], hi[4];
#pragma unroll
            for (int c = 0; c < 4; c++)
                asm("mov.b64 {%0, %1}, %2;" : "=f"(lo[c]), "=f"(hi[c]) : "l"(acc[r][c]));
            float4 o1, o2;
            o1.x = fmaxf(lo[0], 0.f); o1.y = fmaxf(hi[0], 0.f);
            o1.z = fmaxf(lo[1], 0.f); o1.w = fmaxf(hi[1], 0.f);
            o2.x = fmaxf(lo[2], 0.f); o2.y = fmaxf(hi[2], 0.f);
            o2.z = fmaxf(lo[3], 0.f); o2.w = fmaxf(hi[3], 0.f);
            float* p = out + (size_t)grow * D + cg * 8;
            *reinterpret_cast<float4*>(p)     = o1;
            *reinterpret_cast<float4*>(p + 4) = o2;
        }
    }
}

// ---------------------------------------------------------------------------
extern "C" void kernel_launch(void* const* d_in, const int* in_sizes, int n_in,
                              void* d_out, int out_size) {
    // Bind inputs by element count (robust to ordering), positional fallback.
    int ix = -1, ie = -1, iW[3] = {-1, -1, -1}, ib[3] = {-1, -1, -1};
    int nW = 0, nb = 0;
    for (int i = 0; i < n_in; i++) {
        int s = in_sizes[i];
        if (s == N_NODES * D)          ix = i;
        else if (s == 2 * N_EDGES)     ie = i;
        else if (s == D * D && nW < 3) iW[nW++] = i;
        else if (s == D && nb < 3)     ib[nb++] = i;
    }
    if (ix < 0 || ie < 0 || nW < 3 || nb < 3) {
        ix = 0; ie = 1;
        iW[0] = 2; ib[0] = 3; iW[1] = 4; ib[1] = 5; iW[2] = 6; ib[2] = 7;
    }

    const float* x  = (const float*)d_in[ix];
    const void*  ei = d_in[ie];
    const float* W1 = (const float*)d_in[iW[0]];
    const float* b1 = (const float*)d_in[ib[0]];
    const float* W2 = (const float*)d_in[iW[1]];
    const float* b2 = (const float*)d_in[ib[1]];
    const float* W3 = (const float*)d_in[iW[2]];
    const float* b3 = (const float*)d_in[ib[2]];
    float* out = (float*)d_out;

    const int n = in_sizes[ix] / D;      // 100000
    const int E = in_sizes[ie] / 2;      // 1200000

    const int gemm_blocks   = (n + GR - 1) / GR;
    const int filter_blocks = (n * 16 + 255) / 256;
    const int node_blocks   = (n + 255) / 256;   // = NB for the scan

    // graph prep: dtype probe, degree counts
    detect_dtype_kernel<<<1, 32>>>((const long long*)ei);
    init_counts_kernel<<<node_blocks, 256>>>(n);
    edge_prep_kernel<<<(E + 255) / 256, 256>>>(ei, E, n);

    // layer 1: x -> g_zA
    gemm_relu_kernel<<<gemm_blocks, 128>>>(x, nullptr, W1, b1, n, 0);

    // CSC build: parallel scan + bucket
    scan_partial_kernel<<<node_blocks, 256>>>(n);
    scan_bases_kernel<<<1, NBMAX>>>(node_blocks);
    scan_fill_kernel<<<node_blocks, 256>>>(n);
    bucket_kernel<<<(E + 255) / 256, 256>>>(ei, E, n);

    // filter 1: g_zA -> g_zf (pull, atomic-free)
    filter_kernel<<<filter_blocks, 256>>>(n, 0);

    // layer 2: g_zf -> g_zB
    gemm_relu_kernel<<<gemm_blocks, 128>>>(nullptr, nullptr, W2, b2, n, 1);

    // filter 2: g_zB -> g_zf
    filter_kernel<<<filter_blocks, 256>>>(n, 1);

    // layer 3: g_zf -> d_out
    gemm_relu_kernel<<<gemm_blocks, 128>>>(nullptr, out, W3, b3, n, 2);
}